// round 4
// baseline (speedup 1.0000x reference)
#include <cuda_runtime.h>

// RasterizePointsXYsBlending — point-parallel scatter + parallel composite.
// B=2, P=2048, C=64, SIZE=128, K=8, RADIUS=1.5px, RAD_POW=2, TAU=1.
//
//  1. transpose: src [B,C,P] -> srcT [B,P,C] (smem tile) + zero pixel counters.
//  2. scatter:   thread per (point, bbox-row): exact inside-test on <=4 pixels,
//                atomic append (z, d2, idx) to the pixel's 16-slot list.
//  3. composite: 4 threads per pixel (16 channels each): top-8 by z from the
//                pixel list, compositing weights, float4 gathers, coalesced
//                stores of the full output.

#define BN 2
#define PN 2048
#define CN 64
#define SZ 128
#define KN 8
#define BIGF 1e10f
// r_ndc = 1.5/128*2 = 3*2^-7 ; r2 = 9*2^-14 (exact fp32)
#define R2 0.00054931640625f

#define CAPP 16                         // per-pixel list capacity (mean ~0.9)
#define NPIX (BN * SZ * SZ)             // 32768

__device__ float  d_srcT[BN * PN * CN];         // src transposed to [b,p,c]
__device__ int    d_cnt[NPIX];                  // per-pixel counts
__device__ float4 d_list[NPIX * CAPP];          // (z, d2, bitcast idx, -)

// ---------------------------------------------------------------- kernel 1
// 32x32 tile transpose, block (32,8), grid (P/32, C/32, B) = 256 blocks.
// 65536 threads total — each also zeroes one pixel counter.
__global__ __launch_bounds__(256)
void transpose_kernel(const float* __restrict__ src)
{
    __shared__ float t[32][33];

    const int tid = threadIdx.y * 32 + threadIdx.x;
    const int lid = tid + 256 * (blockIdx.x + 64 * (blockIdx.y + 2 * blockIdx.z));
    d_cnt[lid] = 0;   // lid spans exactly [0, 65536)

    const int p0 = blockIdx.x * 32;
    const int c0 = blockIdx.y * 32;
    const int b  = blockIdx.z;
    const int x  = threadIdx.x;
    const int y  = threadIdx.y;

    const float* sb = src + ((size_t)b * CN << 11);
#pragma unroll
    for (int j = 0; j < 4; ++j)
        t[y + 8 * j][x] = sb[((size_t)(c0 + y + 8 * j) << 11) + p0 + x];
    __syncthreads();

    float* db = d_srcT + (((size_t)b * PN) << 6);
#pragma unroll
    for (int j = 0; j < 4; ++j)
        db[((size_t)(p0 + y + 8 * j) << 6) + c0 + x] = t[x][y + 8 * j];
}

// ---------------------------------------------------------------- kernel 2
// One thread per (point, bbox row offset 0..3). grid = BN*PN*4/128 = 128.
__global__ __launch_bounds__(128)
void scatter_kernel(const float* __restrict__ pts)
{
    const int g  = blockIdx.x * 128 + threadIdx.x;
    const int ry = g & 3;
    const int gp = g >> 2;                 // global point id
    const int b  = gp >> 11;
    const int p  = gp & (PN - 1);

    const float px = -pts[gp * 3 + 0];     // sign flip from the torch forward
    const float py = -pts[gp * 3 + 1];
    const float pz =  pts[gp * 3 + 2];

    // pixel coords of the point: ndc(i) = 1-(2i+1)/128
    const float u = (1.0f - px) * 64.0f - 0.5f;   // w
    const float v = (1.0f - py) * 64.0f - 0.5f;   // h

    // radius 1.5 px + fp margin
    const int wlo = max(0,      (int)ceilf (u - 1.6f));
    const int whi = min(SZ - 1, (int)floorf(u + 1.6f));
    const int hlo = max(0,      (int)ceilf (v - 1.6f));
    const int hhi = min(SZ - 1, (int)floorf(v + 1.6f));

    const int h = hlo + ry;
    if (h > hhi || wlo > whi) return;

    const float ndcy = 1.0f - (2.0f * (float)h + 1.0f) / 128.0f;
    const float dy   = ndcy - py;
    const float dy2  = __fmul_rn(dy, dy);

    for (int w = wlo; w <= whi; ++w) {
        const float ndcx = 1.0f - (2.0f * (float)w + 1.0f) / 128.0f;
        const float dx   = ndcx - px;
        // mul/mul/add, non-fused: matches reference rounding at the boundary
        const float d2 = __fadd_rn(__fmul_rn(dx, dx), dy2);
        if (d2 <= R2) {
            const int pix  = ((b * SZ) + h) * SZ + w;
            const int slot = atomicAdd(&d_cnt[pix], 1);
            if (slot < CAPP)
                d_list[pix * CAPP + slot] =
                    make_float4(pz, d2, __int_as_float(p), 0.0f);
        }
    }
}

// ---------------------------------------------------------------- kernel 3
// Block (32,4): 32 pixels (one output row segment) x 4 channel groups.
// grid = BN*SZ*(SZ/32) = 1024 blocks.
__global__ __launch_bounds__(128)
void composite_kernel(float* __restrict__ out)
{
    const int wt = blockIdx.x & 3;
    const int h  = (blockIdx.x >> 2) & (SZ - 1);
    const int b  = blockIdx.x >> 9;
    const int w  = wt * 32 + threadIdx.x;
    const int cg = threadIdx.y;             // channel group: 16 channels
    const int pix = ((b * SZ) + h) * SZ + w;

    const int cnt = min(d_cnt[pix], CAPP);

    // top-K sorted ascending by z
    float zb[KN], db[KN];
    int   ib[KN];
#pragma unroll
    for (int k = 0; k < KN; ++k) { zb[k] = BIGF; db[k] = 0.0f; ib[k] = 0; }

    const float4* lp = d_list + pix * CAPP;
    for (int i = 0; i < cnt; ++i) {
        float4 e = lp[i];
        if (e.x < zb[KN - 1]) {
            float cz = e.x, cd = e.y;
            int   ci = __float_as_int(e.z);
            bool  ins = false;
#pragma unroll
            for (int k = 0; k < KN; ++k) {
                bool sw = ins | (cz < zb[k]);
                if (sw) {
                    float tz = zb[k]; zb[k] = cz; cz = tz;
                    float td = db[k]; db[k] = cd; cd = td;
                    int   ti = ib[k]; ib[k] = ci; ci = ti;
                    ins = true;
                }
            }
        }
    }

    // compositing weights: w_k = a_k * prod_{j<k}(1 - a_j)
    float wk[KN];
    float T = 1.0f;
#pragma unroll
    for (int k = 0; k < KN; ++k) {
        if (zb[k] < BIGF) {
            float dist = __fdiv_rn(db[k], R2);
            dist = fminf(fmaxf(dist, 0.001f), 1.0f);
            float a = 1.0f - __fsqrt_rn(dist);
            wk[k] = a * T;
            T = T * (1.0f - a);
        } else {
            wk[k] = 0.0f;
        }
    }

    // gather 16 channels (this thread's group) per selected point
    float acc[16];
#pragma unroll
    for (int j = 0; j < 16; ++j) acc[j] = 0.0f;

#pragma unroll
    for (int k = 0; k < KN; ++k) {
        if (wk[k] > 0.0f) {
            const float4* s4 = (const float4*)
                (d_srcT + (((size_t)b * PN + ib[k]) << 6) + cg * 16);
            const float wkk = wk[k];
#pragma unroll
            for (int j = 0; j < 4; ++j) {
                float4 v = s4[j];
                acc[4 * j + 0] = fmaf(wkk, v.x, acc[4 * j + 0]);
                acc[4 * j + 1] = fmaf(wkk, v.y, acc[4 * j + 1]);
                acc[4 * j + 2] = fmaf(wkk, v.z, acc[4 * j + 2]);
                acc[4 * j + 3] = fmaf(wkk, v.w, acc[4 * j + 3]);
            }
        }
    }

    // out[b,c,h,w]; lane = w -> coalesced 128B stores
    float* ob = out + (((size_t)(b * CN + cg * 16)) * SZ + h) * SZ + w;
#pragma unroll
    for (int j = 0; j < 16; ++j)
        ob[(size_t)j * SZ * SZ] = acc[j];
}

// ---------------------------------------------------------------- launch
extern "C" void kernel_launch(void* const* d_in, const int* in_sizes, int n_in,
                              void* d_out, int out_size)
{
    const float* pts = (const float*)d_in[0];  // [B,P,3]
    const float* src = (const float*)d_in[1];  // [B,C,P]
    float* out = (float*)d_out;                // [B,C,H,W]

    transpose_kernel<<<dim3(PN / 32, CN / 32, BN), dim3(32, 8)>>>(src);
    scatter_kernel<<<(BN * PN * 4) / 128, 128>>>(pts);
    composite_kernel<<<BN * SZ * (SZ / 32), dim3(32, 4)>>>(out);
}

// round 5
// speedup vs baseline: 1.2775x; 1.2775x over previous
#include <cuda_runtime.h>

// RasterizePointsXYsBlending — 2-kernel pipeline with counter recycling.
// B=2, P=2048, C=64, SIZE=128, K=8, RADIUS=1.5px, RAD_POW=2, TAU=1.
//
//  K1 (fused, 320 blocks x 256 thr):
//     blocks [0,256):  transpose src [B,C,P] -> srcT [B,P,C] (smem tile)
//     blocks [256,320): scatter — thread per (point, bbox-row): exact
//                       inside-test on <=4 pixels, atomic append
//                       (z, d2, idx) to the pixel's 16-slot list.
//     The two halves are independent; scatter hides in transpose latency.
//  K2 (composite, 1024 blocks x (32,4)):
//     4 threads per pixel (16 channels each): top-8 by z from the pixel
//     list, compositing weights, float4 gathers from srcT, coalesced
//     stores. Resets the pixel counter to 0 after use (d_cnt is
//     zero-initialized at load; every call restores the invariant).

#define BN 2
#define PN 2048
#define CN 64
#define SZ 128
#define KN 8
#define BIGF 1e10f
// r_ndc = 1.5/128*2 = 3*2^-7 ; r2 = 9*2^-14 (exact fp32)
#define R2 0.00054931640625f

#define CAPP 16                       // per-pixel list capacity (mean ~0.9)
#define NPIX (BN * SZ * SZ)           // 32768
#define TRB 256                       // transpose blocks
#define SCB 64                        // scatter blocks (64*256 = BN*PN*4)

__device__ float  d_srcT[BN * PN * CN];   // src transposed to [b,p,c]
__device__ int    d_cnt[NPIX];            // per-pixel counts (invariant: 0)
__device__ float4 d_list[NPIX * CAPP];    // (z, d2, bitcast idx, -)

// ---------------------------------------------------------------- kernel 1
__global__ __launch_bounds__(256)
void prep_kernel(const float* __restrict__ src, const float* __restrict__ pts)
{
    if (blockIdx.x < TRB) {
        // ---------------- transpose half: 32x32 smem tile ----------------
        __shared__ float t[32][33];

        const int x  = threadIdx.x & 31;
        const int y  = threadIdx.x >> 5;           // 0..7
        const int p0 = (blockIdx.x & 63) * 32;     // 64 p-tiles
        const int c0 = ((blockIdx.x >> 6) & 1) * 32; // 2 c-tiles
        const int b  = blockIdx.x >> 7;            // 2 batches

        const float* sb = src + ((size_t)b * CN << 11);
#pragma unroll
        for (int j = 0; j < 4; ++j)
            t[y + 8 * j][x] = sb[((size_t)(c0 + y + 8 * j) << 11) + p0 + x];
        __syncthreads();

        float* db = d_srcT + (((size_t)b * PN) << 6);
#pragma unroll
        for (int j = 0; j < 4; ++j)
            db[((size_t)(p0 + y + 8 * j) << 6) + c0 + x] = t[x][y + 8 * j];
    } else {
        // ---------------- scatter half: (point, bbox-row) ----------------
        const int g  = (blockIdx.x - TRB) * 256 + threadIdx.x;
        const int ry = g & 3;
        const int gp = g >> 2;                 // global point id
        const int b  = gp >> 11;
        const int p  = gp & (PN - 1);

        const float px = -pts[gp * 3 + 0];     // sign flip from the forward
        const float py = -pts[gp * 3 + 1];
        const float pz =  pts[gp * 3 + 2];

        // pixel coords of the point: ndc(i) = 1-(2i+1)/128
        const float u = (1.0f - px) * 64.0f - 0.5f;   // w
        const float v = (1.0f - py) * 64.0f - 0.5f;   // h

        // radius 1.5 px + fp margin
        const int wlo = max(0,      (int)ceilf (u - 1.6f));
        const int whi = min(SZ - 1, (int)floorf(u + 1.6f));
        const int hlo = max(0,      (int)ceilf (v - 1.6f));
        const int hhi = min(SZ - 1, (int)floorf(v + 1.6f));

        const int h = hlo + ry;
        if (h > hhi || wlo > whi) return;

        const float ndcy = 1.0f - (2.0f * (float)h + 1.0f) / 128.0f;
        const float dy   = ndcy - py;
        const float dy2  = __fmul_rn(dy, dy);

        for (int w = wlo; w <= whi; ++w) {
            const float ndcx = 1.0f - (2.0f * (float)w + 1.0f) / 128.0f;
            const float dx   = ndcx - px;
            // mul/mul/add, non-fused: matches reference rounding exactly
            const float d2 = __fadd_rn(__fmul_rn(dx, dx), dy2);
            if (d2 <= R2) {
                const int pix  = ((b * SZ) + h) * SZ + w;
                const int slot = atomicAdd(&d_cnt[pix], 1);
                if (slot < CAPP)
                    d_list[pix * CAPP + slot] =
                        make_float4(pz, d2, __int_as_float(p), 0.0f);
            }
        }
    }
}

// ---------------------------------------------------------------- kernel 2
// Block (32,4): 32 pixels (one output row segment) x 4 channel groups.
// grid = BN*SZ*(SZ/32) = 1024 blocks.
__global__ __launch_bounds__(128)
void composite_kernel(float* __restrict__ out)
{
    const int wt = blockIdx.x & 3;
    const int h  = (blockIdx.x >> 2) & (SZ - 1);
    const int b  = blockIdx.x >> 9;
    const int w  = wt * 32 + threadIdx.x;
    const int cg = threadIdx.y;              // channel group: 16 channels
    const int pix = ((b * SZ) + h) * SZ + w;

    const int cnt = min(d_cnt[pix], CAPP);
    if (cg == 0) d_cnt[pix] = 0;             // restore the all-zero invariant

    // top-K sorted ascending by z
    float zb[KN], db[KN];
    int   ib[KN];
#pragma unroll
    for (int k = 0; k < KN; ++k) { zb[k] = BIGF; db[k] = 0.0f; ib[k] = 0; }

    const float4* lp = d_list + pix * CAPP;
    for (int i = 0; i < cnt; ++i) {
        float4 e = lp[i];
        if (e.x < zb[KN - 1]) {
            float cz = e.x, cd = e.y;
            int   ci = __float_as_int(e.z);
            bool  ins = false;
#pragma unroll
            for (int k = 0; k < KN; ++k) {
                bool sw = ins | (cz < zb[k]);
                if (sw) {
                    float tz = zb[k]; zb[k] = cz; cz = tz;
                    float td = db[k]; db[k] = cd; cd = td;
                    int   ti = ib[k]; ib[k] = ci; ci = ti;
                    ins = true;
                }
            }
        }
    }

    // compositing weights: w_k = a_k * prod_{j<k}(1 - a_j)
    float wk[KN];
    float T = 1.0f;
#pragma unroll
    for (int k = 0; k < KN; ++k) {
        if (zb[k] < BIGF) {
            float dist = __fdiv_rn(db[k], R2);
            dist = fminf(fmaxf(dist, 0.001f), 1.0f);
            float a = 1.0f - __fsqrt_rn(dist);
            wk[k] = a * T;
            T = T * (1.0f - a);
        } else {
            wk[k] = 0.0f;
        }
    }

    // gather 16 channels (this thread's group) per selected point
    float acc[16];
#pragma unroll
    for (int j = 0; j < 16; ++j) acc[j] = 0.0f;

#pragma unroll
    for (int k = 0; k < KN; ++k) {
        if (wk[k] > 0.0f) {
            const float4* s4 = (const float4*)
                (d_srcT + (((size_t)b * PN + ib[k]) << 6) + cg * 16);
            const float wkk = wk[k];
#pragma unroll
            for (int j = 0; j < 4; ++j) {
                float4 v = s4[j];
                acc[4 * j + 0] = fmaf(wkk, v.x, acc[4 * j + 0]);
                acc[4 * j + 1] = fmaf(wkk, v.y, acc[4 * j + 1]);
                acc[4 * j + 2] = fmaf(wkk, v.z, acc[4 * j + 2]);
                acc[4 * j + 3] = fmaf(wkk, v.w, acc[4 * j + 3]);
            }
        }
    }

    // out[b,c,h,w]; lane = w -> coalesced 128B stores
    float* ob = out + (((size_t)(b * CN + cg * 16)) * SZ + h) * SZ + w;
#pragma unroll
    for (int j = 0; j < 16; ++j)
        ob[(size_t)j * SZ * SZ] = acc[j];
}

// ---------------------------------------------------------------- launch
extern "C" void kernel_launch(void* const* d_in, const int* in_sizes, int n_in,
                              void* d_out, int out_size)
{
    const float* pts = (const float*)d_in[0];  // [B,P,3]
    const float* src = (const float*)d_in[1];  // [B,C,P]
    float* out = (float*)d_out;                // [B,C,H,W]

    prep_kernel<<<TRB + SCB, 256>>>(src, pts);
    composite_kernel<<<BN * SZ * (SZ / 32), dim3(32, 4)>>>(out);
}